// round 1
// baseline (speedup 1.0000x reference)
#include <cuda_runtime.h>

// CorrelationHead fused kernel.
// out[b,o] = b_bbox[o] + sum_{c,ij,uv, parity-matched} p1[b,c,ij] * p2[b,c,uv] * w[o, p,q,i,j]
//   with p = (u-i)/2 + 10, q = (v-j)/2 + 10   (u===i mod 2, v===j mod 2, else w-coeff is 0
//   because the displaced patch2 sample never lands on that (u,v)).
//
// Per-batch 49x49 Gram restricted to 4 parity classes (16x16, 12x12, 12x12, 9x9 = 625 pairs),
// contracted against the 4 weight rows without materializing corr or G.

#define NB       512
#define NC       128
#define HW       49
#define FEAT     21609   // 21*21*7*7
#define SSTR     52      // smem row stride (padded from 49)
#define CCH      64      // channel chunk (2 chunks of 64)
#define NTHREADS 256

// packed parity-class layout: class (pi,pj) bases: (0,0)->0 [16], (0,1)->16 [12],
// (1,0)->28 [12], (1,1)->40 [9]
__device__ __forceinline__ int perm49(int pos) {
    int i = pos / 7, j = pos - (pos / 7) * 7;
    int pi = i & 1, pj = j & 1;
    int ri = i >> 1, rj = j >> 1;
    int base = pi ? (pj ? 40 : 28) : (pj ? 16 : 0);
    int nj = pj ? 3 : 4;
    return base + ri * nj + rj;
}

// contract one Gram entry g at (local row r, local col s) of class (pi,pj) with the 4 weight rows
__device__ __forceinline__ void accum_pair(float lacc[4], float g, int r, int s,
                                           int pi, int pj, int nj,
                                           const float* __restrict__ w) {
    int ri = r / nj, rj = r - (r / nj) * nj;
    int su = s / nj, sv = s - (s / nj) * nj;
    int i = 2 * ri + pi, j = 2 * rj + pj;
    int p = su - ri + 10, q = sv - rj + 10;
    int widx = ((p * 21 + q) * 7 + i) * 7 + j;
#pragma unroll
    for (int o = 0; o < 4; o++) lacc[o] += g * __ldg(&w[o * FEAT + widx]);
}

__global__ __launch_bounds__(NTHREADS) void corr_head_kernel(
    const float* __restrict__ p1, const float* __restrict__ p2,
    const float* __restrict__ w, const float* __restrict__ bb,
    float* __restrict__ out)
{
    __shared__ float s1[CCH * SSTR];
    __shared__ float s2[CCH * SSTR];
    __shared__ float sred[8][4];

    const int tid = threadIdx.x;
    const int b = blockIdx.x;

    const float4* p14 = (const float4*)(p1 + (size_t)b * NC * HW);
    const float4* p24 = (const float4*)(p2 + (size_t)b * NC * HW);

    // Gram accumulators (up to 9 for the 3x3-tiled class)
    float g[9];
#pragma unroll
    for (int k = 0; k < 9; k++) g[k] = 0.f;

    for (int chunk = 0; chunk < NC / CCH; chunk++) {
        // ---- load 64 channels x 49 positions of both tensors, permuted into class layout ----
        const int base4 = chunk * (CCH * HW / 4);   // 784 float4 per tensor per chunk
        for (int idx4 = tid; idx4 < CCH * HW / 4; idx4 += NTHREADS) {
            float4 v1 = p14[base4 + idx4];
            float4 v2 = p24[base4 + idx4];
            int lin = idx4 * 4;
#pragma unroll
            for (int k = 0; k < 4; k++) {
                int e = lin + k;
                int cc = e / HW;
                int pos = e - cc * HW;
                int pk = cc * SSTR + perm49(pos);
                s1[pk] = (&v1.x)[k];
                s2[pk] = (&v2.x)[k];
            }
        }
        __syncthreads();

        // ---- per-class Gram micro-GEMMs (register tiles, accumulate over this chunk) ----
        if (tid < 64) {
            // class (0,0): 16x16, 2x2 tiles, 8x8 threads
            int ty = tid >> 3, tx = tid & 7;
            const float* r1 = s1 + ty;        // base 0
            const float* r2 = s2 + tx;
#pragma unroll 4
            for (int c = 0; c < CCH; c++) {
                float a0 = r1[c * SSTR],     a1 = r1[c * SSTR + 8];
                float b0 = r2[c * SSTR],     b1 = r2[c * SSTR + 8];
                g[0] += a0 * b0; g[1] += a0 * b1;
                g[2] += a1 * b0; g[3] += a1 * b1;
            }
        } else if (tid < 100) {
            // class (0,1): 12x12, 2x2 tiles, 6x6 threads
            int t = tid - 64;
            int ty = t / 6, tx = t - (t / 6) * 6;
            const float* r1 = s1 + 16 + ty;
            const float* r2 = s2 + 16 + tx;
#pragma unroll 4
            for (int c = 0; c < CCH; c++) {
                float a0 = r1[c * SSTR],     a1 = r1[c * SSTR + 6];
                float b0 = r2[c * SSTR],     b1 = r2[c * SSTR + 6];
                g[0] += a0 * b0; g[1] += a0 * b1;
                g[2] += a1 * b0; g[3] += a1 * b1;
            }
        } else if (tid < 136) {
            // class (1,0): 12x12, 2x2 tiles, 6x6 threads
            int t = tid - 100;
            int ty = t / 6, tx = t - (t / 6) * 6;
            const float* r1 = s1 + 28 + ty;
            const float* r2 = s2 + 28 + tx;
#pragma unroll 4
            for (int c = 0; c < CCH; c++) {
                float a0 = r1[c * SSTR],     a1 = r1[c * SSTR + 6];
                float b0 = r2[c * SSTR],     b1 = r2[c * SSTR + 6];
                g[0] += a0 * b0; g[1] += a0 * b1;
                g[2] += a1 * b0; g[3] += a1 * b1;
            }
        } else if (tid < 145) {
            // class (1,1): 9x9, 3x3 tiles, 3x3 threads
            int t = tid - 136;
            int ty = t / 3, tx = t - (t / 3) * 3;
            const float* r1 = s1 + 40 + ty;
            const float* r2 = s2 + 40 + tx;
#pragma unroll 4
            for (int c = 0; c < CCH; c++) {
                float a0 = r1[c * SSTR], a1 = r1[c * SSTR + 3], a2 = r1[c * SSTR + 6];
                float b0 = r2[c * SSTR], b1 = r2[c * SSTR + 3], b2 = r2[c * SSTR + 6];
                g[0] += a0 * b0; g[1] += a0 * b1; g[2] += a0 * b2;
                g[3] += a1 * b0; g[4] += a1 * b1; g[5] += a1 * b2;
                g[6] += a2 * b0; g[7] += a2 * b1; g[8] += a2 * b2;
            }
        }
        __syncthreads();
    }

    // ---- contract Gram tiles with weight rows (w working set is 10KB, L2-resident) ----
    float lacc[4] = {0.f, 0.f, 0.f, 0.f};
    if (tid < 64) {
        int ty = tid >> 3, tx = tid & 7;
        accum_pair(lacc, g[0], ty,     tx,     0, 0, 4, w);
        accum_pair(lacc, g[1], ty,     tx + 8, 0, 0, 4, w);
        accum_pair(lacc, g[2], ty + 8, tx,     0, 0, 4, w);
        accum_pair(lacc, g[3], ty + 8, tx + 8, 0, 0, 4, w);
    } else if (tid < 100) {
        int t = tid - 64;
        int ty = t / 6, tx = t - (t / 6) * 6;
        accum_pair(lacc, g[0], ty,     tx,     0, 1, 3, w);
        accum_pair(lacc, g[1], ty,     tx + 6, 0, 1, 3, w);
        accum_pair(lacc, g[2], ty + 6, tx,     0, 1, 3, w);
        accum_pair(lacc, g[3], ty + 6, tx + 6, 0, 1, 3, w);
    } else if (tid < 136) {
        int t = tid - 100;
        int ty = t / 6, tx = t - (t / 6) * 6;
        accum_pair(lacc, g[0], ty,     tx,     1, 0, 4, w);
        accum_pair(lacc, g[1], ty,     tx + 6, 1, 0, 4, w);
        accum_pair(lacc, g[2], ty + 6, tx,     1, 0, 4, w);
        accum_pair(lacc, g[3], ty + 6, tx + 6, 1, 0, 4, w);
    } else if (tid < 145) {
        int t = tid - 136;
        int ty = t / 3, tx = t - (t / 3) * 3;
        accum_pair(lacc, g[0], ty,     tx,     1, 1, 3, w);
        accum_pair(lacc, g[1], ty,     tx + 3, 1, 1, 3, w);
        accum_pair(lacc, g[2], ty,     tx + 6, 1, 1, 3, w);
        accum_pair(lacc, g[3], ty + 3, tx,     1, 1, 3, w);
        accum_pair(lacc, g[4], ty + 3, tx + 3, 1, 1, 3, w);
        accum_pair(lacc, g[5], ty + 3, tx + 6, 1, 1, 3, w);
        accum_pair(lacc, g[6], ty + 6, tx,     1, 1, 3, w);
        accum_pair(lacc, g[7], ty + 6, tx + 3, 1, 1, 3, w);
        accum_pair(lacc, g[8], ty + 6, tx + 6, 1, 1, 3, w);
    }

    // ---- deterministic tree reduction of the 4 partial outputs ----
#pragma unroll
    for (int off = 16; off; off >>= 1) {
#pragma unroll
        for (int o = 0; o < 4; o++)
            lacc[o] += __shfl_down_sync(0xffffffffu, lacc[o], off);
    }
    int warp = tid >> 5, lane = tid & 31;
    if (lane == 0) {
#pragma unroll
        for (int o = 0; o < 4; o++) sred[warp][o] = lacc[o];
    }
    __syncthreads();
    if (tid < 4) {
        float sres = bb[tid];
#pragma unroll
        for (int wi = 0; wi < 8; wi++) sres += sred[wi][tid];
        out[b * 4 + tid] = sres;
    }
}

extern "C" void kernel_launch(void* const* d_in, const int* in_sizes, int n_in,
                              void* d_out, int out_size) {
    const float* p1 = (const float*)d_in[0];   // patch1 [512,128,7,7]
    const float* p2 = (const float*)d_in[1];   // patch2 [512,128,7,7]
    const float* w  = (const float*)d_in[2];   // w_bbox [4,21609]
    const float* bb = (const float*)d_in[3];   // b_bbox [4]
    float* out = (float*)d_out;                // [512,4] float32

    corr_head_kernel<<<NB, NTHREADS>>>(p1, p2, w, bb, out);
}